// round 2
// baseline (speedup 1.0000x reference)
#include <cuda_runtime.h>
#include <cstdint>

#define BT20   2621440u     // B*20 (elements per head slab)
#define HALFN  52428800u    // 20*BT20
#define TPB    128

// ---- packed f32x2 helpers (Blackwell FFMA2) ----
__device__ __forceinline__ unsigned long long pack2(float lo, float hi) {
    unsigned long long r;
    asm("mov.b64 %0, {%1, %2};" : "=l"(r) : "f"(lo), "f"(hi));
    return r;
}
__device__ __forceinline__ void unpack2(unsigned long long v, float &lo, float &hi) {
    asm("mov.b64 {%0, %1}, %2;" : "=f"(lo), "=f"(hi) : "l"(v));
}
__device__ __forceinline__ void fma2(unsigned long long &d, unsigned long long a,
                                     unsigned long long b) {
    asm("fma.rn.f32x2 %0, %1, %2, %0;" : "+l"(d) : "l"(a), "l"(b));
}

// ---- Threefry-2x32-20, key (0, 42) == raw data of jax.random.key(42) ----
__device__ __forceinline__ void threefry_0_42(uint32_t c0, uint32_t c1,
                                              uint32_t &o0, uint32_t &o1) {
    const uint32_t ks0 = 0u;
    const uint32_t ks1 = 42u;
    const uint32_t ks2 = 0x1BD11BDAu ^ 42u;
    uint32_t x0 = c0 + ks0;
    uint32_t x1 = c1 + ks1;
#define TF_ROUND(r) { x0 += x1; x1 = __funnelshift_l(x1, x1, (r)); x1 ^= x0; }
    TF_ROUND(13) TF_ROUND(15) TF_ROUND(26) TF_ROUND(6)
    x0 += ks1; x1 += ks2 + 1u;
    TF_ROUND(17) TF_ROUND(29) TF_ROUND(16) TF_ROUND(24)
    x0 += ks2; x1 += ks0 + 2u;
    TF_ROUND(13) TF_ROUND(15) TF_ROUND(26) TF_ROUND(6)
    x0 += ks0; x1 += ks1 + 3u;
    TF_ROUND(17) TF_ROUND(29) TF_ROUND(16) TF_ROUND(24)
    x0 += ks1; x1 += ks2 + 4u;
    TF_ROUND(13) TF_ROUND(15) TF_ROUND(26) TF_ROUND(6)
    x0 += ks2; x1 += ks0 + 5u;
#undef TF_ROUND
    o0 = x0; o1 = x1;
}

// Partitionable threefry random_bits (jax_threefry_partitionable=True, the
// default since JAX 0.4.30): per-element 64-bit counter (hi=0 for n < 2^32),
// 32-bit sample = xor of the two threefry output words.
__device__ __forceinline__ uint32_t tf_bits_partitionable(uint32_t j) {
    uint32_t o0, o1;
    threefry_0_42(0u, j, o0, o1);
    return o0 ^ o1;
}

__global__ __launch_bounds__(TPB, 4)
void fused_mlp_dropout(const float* __restrict__ x,
                       const float* __restrict__ W1,
                       const float* __restrict__ b1,
                       const float* __restrict__ Wh,
                       const float* __restrict__ bh,
                       float* __restrict__ out)
{
    __shared__ __align__(16) float sW1[1200];   // [60][20]
    __shared__           float sb1[64];
    __shared__ __align__(16) float sbh[800];    // [40][20]
    __shared__ __align__(16) float sWhA[1200];  // Wh[k]      [20][60]
    __shared__ __align__(16) float sWhB[1200];  // Wh[k+20]   [20][60]

    const int tid = threadIdx.x;

    // cooperative constant loads
    for (int i = tid; i < 300; i += TPB)
        ((float4*)sW1)[i] = ((const float4*)W1)[i];
    for (int i = tid; i < 200; i += TPB)
        ((float4*)sbh)[i] = ((const float4*)bh)[i];
    if (tid < 60) sb1[tid] = b1[tid];
    __syncthreads();

    const unsigned b = blockIdx.x * TPB + tid;   // one row per thread

    // ---- load x row (20 floats, 80B rows, 16B aligned) ----
    float xr[20];
    {
        const float4* xp = (const float4*)(x + (size_t)b * 20);
        #pragma unroll
        for (int i = 0; i < 5; i++) {
            float4 v = xp[i];
            xr[i*4+0] = v.x; xr[i*4+1] = v.y; xr[i*4+2] = v.z; xr[i*4+3] = v.w;
        }
    }
    unsigned long long x2[10];
    #pragma unroll
    for (int i = 0; i < 10; i++) x2[i] = pack2(xr[2*i], xr[2*i+1]);

    // ---- trunk: h = relu(W1 @ x + b1), packed as 30 f32x2 regs ----
    unsigned long long h2[30];
    #pragma unroll
    for (int i = 0; i < 30; i++) {
        unsigned long long a0 = 0ull, a1 = 0ull;
        const unsigned long long* w0  = (const unsigned long long*)(sW1 + (2*i)   * 20);
        const unsigned long long* w1r = (const unsigned long long*)(sW1 + (2*i+1) * 20);
        #pragma unroll
        for (int d = 0; d < 10; d++) {
            fma2(a0, x2[d], w0[d]);
            fma2(a1, x2[d], w1r[d]);
        }
        float s0a, s0b, s1a, s1b;
        unpack2(a0, s0a, s0b);
        unpack2(a1, s1a, s1b);
        float hv0 = fmaxf(s0a + s0b + sb1[2*i],   0.f);
        float hv1 = fmaxf(s1a + s1b + sb1[2*i+1], 0.f);
        h2[i] = pack2(hv0, hv1);
    }

    const unsigned base_b = b * 20u;

    // ---- heads: process k and k+20 per iteration (shared smem staging) ----
    for (int k = 0; k < 20; k++) {
        __syncthreads();   // protect previous iteration's sWh reads
        const float4* srcA = (const float4*)(Wh + (size_t)k        * 1200);
        const float4* srcB = (const float4*)(Wh + (size_t)(k + 20) * 1200);
        for (int i = tid; i < 300; i += TPB) {
            ((float4*)sWhA)[i] = srcA[i];
            ((float4*)sWhB)[i] = srcB[i];
        }
        __syncthreads();

        #pragma unroll 1
        for (int oc = 0; oc < 5; oc++) {
            float y0v[4], y1v[4];
            #pragma unroll
            for (int u = 0; u < 4; u++) {
                const int o = oc * 4 + u;
                const unsigned long long* wA =
                    (const unsigned long long*)(sWhA + o * 60);
                const unsigned long long* wB =
                    (const unsigned long long*)(sWhB + o * 60);
                unsigned long long a0 = 0ull, a0b = 0ull, a1 = 0ull, a1b = 0ull;
                #pragma unroll
                for (int d = 0; d < 15; d++) {
                    fma2(a0,  wA[2*d],   h2[2*d]);
                    fma2(a0b, wA[2*d+1], h2[2*d+1]);
                    fma2(a1,  wB[2*d],   h2[2*d]);
                    fma2(a1b, wB[2*d+1], h2[2*d+1]);
                }
                float p0,q0,p1,q1,p2,q2,p3,q3;
                unpack2(a0,  p0, q0); unpack2(a0b, p1, q1);
                unpack2(a1,  p2, q2); unpack2(a1b, p3, q3);
                float accA = (p0 + q0) + (p1 + q1) + sbh[k*20 + o];
                float accB = (p2 + q2) + (p3 + q3) + sbh[(k+20)*20 + o];

                // partitionable threefry: one full block per element
                uint32_t jA = (unsigned)k * BT20 + base_b + (unsigned)o;
                uint32_t rA = tf_bits_partitionable(jA);
                uint32_t rB = tf_bits_partitionable(jA + HALFN);

                // keep iff MSB==0; inverted dropout scale = 2.0
                y0v[u] = ((int)rA >= 0) ? fmaxf(accA, 0.f) * 2.f : 0.f;
                y1v[u] = ((int)rB >= 0) ? fmaxf(accB, 0.f) * 2.f : 0.f;
            }
            float4 v0 = make_float4(y0v[0], y0v[1], y0v[2], y0v[3]);
            float4 v1 = make_float4(y1v[0], y1v[1], y1v[2], y1v[3]);
            *(float4*)(out + (size_t)k        * BT20 + base_b + oc * 4) = v0;
            *(float4*)(out + (size_t)(k + 20) * BT20 + base_b + oc * 4) = v1;
        }
    }
}

extern "C" void kernel_launch(void* const* d_in, const int* in_sizes, int n_in,
                              void* d_out, int out_size) {
    const float* x  = (const float*)d_in[0];   // [131072, 20]
    const float* W1 = (const float*)d_in[1];   // [60, 20]
    const float* b1 = (const float*)d_in[2];   // [60]
    const float* Wh = (const float*)d_in[3];   // [40, 20, 60]
    const float* bh = (const float*)d_in[4];   // [40, 20]
    float* out = (float*)d_out;                // [40, 131072, 1, 20]

    const int rows = in_sizes[0] / 20;         // 131072
    dim3 grid(rows / TPB), block(TPB);
    fused_mlp_dropout<<<grid, block>>>(x, W1, b1, Wh, bh, out);
}

// round 3
// speedup vs baseline: 1.0062x; 1.0062x over previous
#include <cuda_runtime.h>
#include <cstdint>

#define BT20   2621440u     // B*20 (elements per head slab)
#define HALFN  52428800u    // 20*BT20
#define TPB    64

// ---- packed f32x2 helpers (Blackwell FFMA2) ----
__device__ __forceinline__ unsigned long long pack2(float lo, float hi) {
    unsigned long long r;
    asm("mov.b64 %0, {%1, %2};" : "=l"(r) : "f"(lo), "f"(hi));
    return r;
}
__device__ __forceinline__ void unpack2(unsigned long long v, float &lo, float &hi) {
    asm("mov.b64 {%0, %1}, %2;" : "=f"(lo), "=f"(hi) : "l"(v));
}
__device__ __forceinline__ void fma2(unsigned long long &d, unsigned long long a,
                                     unsigned long long b) {
    asm("fma.rn.f32x2 %0, %1, %2, %0;" : "+l"(d) : "l"(a), "l"(b));
}
__device__ __forceinline__ unsigned long long f2lo(const float4 &v) { return pack2(v.x, v.y); }
__device__ __forceinline__ unsigned long long f2hi(const float4 &v) { return pack2(v.z, v.w); }

// add via IMAD with runtime "one" -> lands on the FMA pipe (IADD3 is alu-pipe)
__device__ __forceinline__ uint32_t addm(uint32_t a, uint32_t b, uint32_t one) {
    uint32_t r;
    asm("mad.lo.u32 %0, %1, %2, %3;" : "=r"(r) : "r"(b), "r"(one), "r"(a));
    return r;
}

// ---- Threefry-2x32-20, key (0, 42); round-adds forced onto fma pipe ----
__device__ __forceinline__ uint32_t tf_bits_partitionable(uint32_t j, uint32_t one) {
    const uint32_t ks1 = 42u;
    const uint32_t ks2 = 0x1BD11BDAu ^ 42u;
    uint32_t x0 = 0u;          // c0 + ks0
    uint32_t x1 = j + ks1;     // c1 + ks1
#define TF_ROUND(r) { x0 = addm(x0, x1, one); \
                      x1 = __funnelshift_l(x1, x1, (r)); x1 ^= x0; }
    TF_ROUND(13) TF_ROUND(15) TF_ROUND(26) TF_ROUND(6)
    x0 += ks1; x1 += ks2 + 1u;
    TF_ROUND(17) TF_ROUND(29) TF_ROUND(16) TF_ROUND(24)
    x0 += ks2; x1 += 0u + 2u;
    TF_ROUND(13) TF_ROUND(15) TF_ROUND(26) TF_ROUND(6)
    x0 += 0u; x1 += ks1 + 3u;
    TF_ROUND(17) TF_ROUND(29) TF_ROUND(16) TF_ROUND(24)
    x0 += ks1; x1 += ks2 + 4u;
    TF_ROUND(13) TF_ROUND(15) TF_ROUND(26) TF_ROUND(6)
    x0 += ks2; x1 += 0u + 5u;
#undef TF_ROUND
    return x0 ^ x1;   // partitionable random_bits: xor of the two output words
}

__global__ __launch_bounds__(TPB, 10)
void fused_mlp_dropout(const float* __restrict__ x,
                       const float* __restrict__ W1,
                       const float* __restrict__ b1,
                       const float* __restrict__ Wh,
                       const float* __restrict__ bh,
                       float* __restrict__ out,
                       uint32_t one)
{
    __shared__ __align__(16) float sW1[1200];   // [60][20]
    __shared__           float sb1[64];
    __shared__ __align__(16) float sbh[800];    // [40][20]
    __shared__ __align__(16) float sWhA[1200];  // Wh[k]      [20][60]
    __shared__ __align__(16) float sWhB[1200];  // Wh[k+20]   [20][60]

    const int tid = threadIdx.x;

    for (int i = tid; i < 300; i += TPB)
        ((float4*)sW1)[i] = ((const float4*)W1)[i];
    for (int i = tid; i < 200; i += TPB)
        ((float4*)sbh)[i] = ((const float4*)bh)[i];
    if (tid < 60) sb1[tid] = b1[tid];
    __syncthreads();

    const unsigned b = blockIdx.x * TPB + tid;   // one row per thread

    // ---- load x row (20 floats, 80B rows, 16B aligned) ----
    unsigned long long x2[10];
    {
        const float4* xp = (const float4*)(x + (size_t)b * 20);
        #pragma unroll
        for (int i = 0; i < 5; i++) {
            float4 v = xp[i];
            x2[2*i]   = f2lo(v);
            x2[2*i+1] = f2hi(v);
        }
    }

    // ---- trunk: h = relu(W1 @ x + b1), packed as 30 f32x2 regs ----
    unsigned long long h2[30];
    #pragma unroll
    for (int i = 0; i < 30; i++) {
        unsigned long long a0 = 0ull, a1 = 0ull;
        const float4* w0 = (const float4*)(sW1 + (2*i)   * 20);
        const float4* w1 = (const float4*)(sW1 + (2*i+1) * 20);
        #pragma unroll
        for (int d = 0; d < 5; d++) {
            float4 v0 = w0[d], v1 = w1[d];
            fma2(a0, x2[2*d],   f2lo(v0));
            fma2(a0, x2[2*d+1], f2hi(v0));
            fma2(a1, x2[2*d],   f2lo(v1));
            fma2(a1, x2[2*d+1], f2hi(v1));
        }
        float s0a, s0b, s1a, s1b;
        unpack2(a0, s0a, s0b);
        unpack2(a1, s1a, s1b);
        float hv0 = fmaxf(s0a + s0b + sb1[2*i],   0.f);
        float hv1 = fmaxf(s1a + s1b + sb1[2*i+1], 0.f);
        h2[i] = pack2(hv0, hv1);
    }

    const unsigned base_b = b * 20u;

    // ---- heads: process k and k+20 per iteration ----
    for (int k = 0; k < 20; k++) {
        __syncthreads();   // protect previous iteration's sWh reads
        const float4* srcA = (const float4*)(Wh + (size_t)k        * 1200);
        const float4* srcB = (const float4*)(Wh + (size_t)(k + 20) * 1200);
        for (int i = tid; i < 300; i += TPB) {
            ((float4*)sWhA)[i] = srcA[i];
            ((float4*)sWhB)[i] = srcB[i];
        }
        __syncthreads();

        #pragma unroll 1
        for (int oc = 0; oc < 5; oc++) {
            float y0v[4], y1v[4];
            #pragma unroll
            for (int u = 0; u < 4; u++) {
                const int o = oc * 4 + u;
                const float4* wA4 = (const float4*)(sWhA + o * 60);   // 15 x LDS.128
                const float4* wB4 = (const float4*)(sWhB + o * 60);
                unsigned long long a0 = 0ull, a0b = 0ull, a1 = 0ull, a1b = 0ull;
                #pragma unroll
                for (int d = 0; d < 15; d++) {
                    float4 va = wA4[d];
                    float4 vb = wB4[d];
                    fma2(a0,  f2lo(va), h2[2*d]);
                    fma2(a0b, f2hi(va), h2[2*d+1]);
                    fma2(a1,  f2lo(vb), h2[2*d]);
                    fma2(a1b, f2hi(vb), h2[2*d+1]);
                }
                float p0,q0,p1,q1,p2,q2,p3,q3;
                unpack2(a0,  p0, q0); unpack2(a0b, p1, q1);
                unpack2(a1,  p2, q2); unpack2(a1b, p3, q3);
                float accA = (p0 + q0) + (p1 + q1) + sbh[k*20 + o];
                float accB = (p2 + q2) + (p3 + q3) + sbh[(k+20)*20 + o];

                uint32_t jA = (unsigned)k * BT20 + base_b + (unsigned)o;
                uint32_t rA = tf_bits_partitionable(jA,         one);
                uint32_t rB = tf_bits_partitionable(jA + HALFN, one);

                // keep iff MSB==0; inverted dropout scale = 2.0
                y0v[u] = ((int)rA >= 0) ? fmaxf(accA, 0.f) * 2.f : 0.f;
                y1v[u] = ((int)rB >= 0) ? fmaxf(accB, 0.f) * 2.f : 0.f;
            }
            float4 v0 = make_float4(y0v[0], y0v[1], y0v[2], y0v[3]);
            float4 v1 = make_float4(y1v[0], y1v[1], y1v[2], y1v[3]);
            *(float4*)(out + (size_t)k        * BT20 + base_b + oc * 4) = v0;
            *(float4*)(out + (size_t)(k + 20) * BT20 + base_b + oc * 4) = v1;
        }
    }
}

extern "C" void kernel_launch(void* const* d_in, const int* in_sizes, int n_in,
                              void* d_out, int out_size) {
    const float* x  = (const float*)d_in[0];   // [131072, 20]
    const float* W1 = (const float*)d_in[1];   // [60, 20]
    const float* b1 = (const float*)d_in[2];   // [60]
    const float* Wh = (const float*)d_in[3];   // [40, 20, 60]
    const float* bh = (const float*)d_in[4];   // [40, 20]
    float* out = (float*)d_out;                // [40, 131072, 1, 20]

    const int rows = in_sizes[0] / 20;         // 131072
    dim3 grid(rows / TPB), block(TPB);
    fused_mlp_dropout<<<grid, block>>>(x, W1, b1, Wh, bh, out, 1u);
}

// round 4
// speedup vs baseline: 1.0350x; 1.0286x over previous
#include <cuda_runtime.h>
#include <cstdint>

#define BT20   2621440u     // B*20 (elements per head slab)
#define HALFN  52428800u    // 20*BT20
#define TPB    64

// ---- packed f32x2 helpers (Blackwell FFMA2) ----
__device__ __forceinline__ unsigned long long pack2(float lo, float hi) {
    unsigned long long r;
    asm("mov.b64 %0, {%1, %2};" : "=l"(r) : "f"(lo), "f"(hi));
    return r;
}
__device__ __forceinline__ void unpack2(unsigned long long v, float &lo, float &hi) {
    asm("mov.b64 {%0, %1}, %2;" : "=f"(lo), "=f"(hi) : "l"(v));
}
__device__ __forceinline__ void fma2(unsigned long long &d, unsigned long long a,
                                     unsigned long long b) {
    asm("fma.rn.f32x2 %0, %1, %2, %0;" : "+l"(d) : "l"(a), "l"(b));
}
__device__ __forceinline__ void add2(unsigned long long &d, unsigned long long a) {
    asm("add.rn.f32x2 %0, %0, %1;" : "+l"(d) : "l"(a));
}
__device__ __forceinline__ unsigned long long f2lo(const float4 &v) { return pack2(v.x, v.y); }
__device__ __forceinline__ unsigned long long f2hi(const float4 &v) { return pack2(v.z, v.w); }

// add via IMAD with runtime "one" -> lands on the FMA pipe (IADD3 is alu-pipe)
__device__ __forceinline__ uint32_t addm(uint32_t a, uint32_t b, uint32_t one) {
    uint32_t r;
    asm("mad.lo.u32 %0, %1, %2, %3;" : "=r"(r) : "r"(b), "r"(one), "r"(a));
    return r;
}

// ---- Threefry-2x32-20, key (0, 42), partitionable random_bits ----
__device__ __forceinline__ uint32_t tf_bits(uint32_t j, uint32_t one) {
    const uint32_t ks1 = 42u;
    const uint32_t ks2 = 0x1BD11BDAu ^ 42u;
    uint32_t x0 = 0u;          // c0 + ks0
    uint32_t x1 = j + ks1;     // c1 + ks1
#define TF_ROUND(r) { x0 = addm(x0, x1, one); \
                      x1 = __funnelshift_l(x1, x1, (r)); x1 ^= x0; }
    TF_ROUND(13) TF_ROUND(15) TF_ROUND(26) TF_ROUND(6)
    x0 += ks1; x1 += ks2 + 1u;
    TF_ROUND(17) TF_ROUND(29) TF_ROUND(16) TF_ROUND(24)
    x0 += ks2; x1 += 0u + 2u;
    TF_ROUND(13) TF_ROUND(15) TF_ROUND(26) TF_ROUND(6)
    x0 += 0u; x1 += ks1 + 3u;
    TF_ROUND(17) TF_ROUND(29) TF_ROUND(16) TF_ROUND(24)
    x0 += ks1; x1 += ks2 + 4u;
    TF_ROUND(13) TF_ROUND(15) TF_ROUND(26) TF_ROUND(6)
    x0 += ks2; x1 += 0u + 5u;
#undef TF_ROUND
    return x0 ^ x1;   // xor of the two threefry output words
}

__global__ __launch_bounds__(TPB, 9)
void fused_mlp_dropout(const float* __restrict__ x,
                       const float* __restrict__ W1,
                       const float* __restrict__ b1,
                       const float* __restrict__ Wh,
                       const float* __restrict__ bh,
                       float* __restrict__ out,
                       uint32_t one)
{
    __shared__ __align__(16) float sW1[1200];   // [60][20]
    __shared__           float sb1[64];
    __shared__ __align__(16) float sbh[800];    // [40][20]
    __shared__ __align__(16) float sWhA[1200];  // Wh[k]      [20][60]
    __shared__ __align__(16) float sWhB[1200];  // Wh[k+20]   [20][60]

    const int tid = threadIdx.x;

    for (int i = tid; i < 300; i += TPB)
        ((float4*)sW1)[i] = ((const float4*)W1)[i];
    for (int i = tid; i < 200; i += TPB)
        ((float4*)sbh)[i] = ((const float4*)bh)[i];
    if (tid < 60) sb1[tid] = b1[tid];
    __syncthreads();

    const unsigned b = blockIdx.x * TPB + tid;   // one row per thread

    // ---- load x row (20 floats) ----
    unsigned long long x2[10];
    {
        const float4* xp = (const float4*)(x + (size_t)b * 20);
        #pragma unroll
        for (int i = 0; i < 5; i++) {
            float4 v = xp[i];
            x2[2*i]   = f2lo(v);
            x2[2*i+1] = f2hi(v);
        }
    }

    // ---- trunk: h = relu(W1 @ x + b1), packed as 30 f32x2 regs ----
    unsigned long long h2[30];
    #pragma unroll
    for (int i = 0; i < 30; i++) {
        unsigned long long a0 = 0ull, a1 = 0ull;
        const float4* w0 = (const float4*)(sW1 + (2*i)   * 20);
        const float4* w1 = (const float4*)(sW1 + (2*i+1) * 20);
        #pragma unroll
        for (int d = 0; d < 5; d++) {
            float4 v0 = w0[d], v1 = w1[d];
            fma2(a0, x2[2*d],   f2lo(v0));
            fma2(a0, x2[2*d+1], f2hi(v0));
            fma2(a1, x2[2*d],   f2lo(v1));
            fma2(a1, x2[2*d+1], f2hi(v1));
        }
        float s0a, s0b, s1a, s1b;
        unpack2(a0, s0a, s0b);
        unpack2(a1, s1a, s1b);
        float hv0 = fmaxf(s0a + s0b + sb1[2*i],   0.f);
        float hv1 = fmaxf(s1a + s1b + sb1[2*i+1], 0.f);
        h2[i] = pack2(hv0, hv1);
    }

    const unsigned base_b = b * 20u;

    // ---- software-pipelined RNG: tfc holds mask bits for current (k,oc) ----
    uint32_t tfc[8];
    #pragma unroll
    for (int u = 0; u < 4; u++) {               // (k=0, oc=0)
        uint32_t j = base_b + (unsigned)u;
        tfc[2*u]   = tf_bits(j,         one);
        tfc[2*u+1] = tf_bits(j + HALFN, one);
    }

    for (int k = 0; k < 20; k++) {
        __syncthreads();   // protect previous iteration's sWh reads
        const float4* srcA = (const float4*)(Wh + (size_t)k        * 1200);
        const float4* srcB = (const float4*)(Wh + (size_t)(k + 20) * 1200);
        for (int i = tid; i < 300; i += TPB) {
            ((float4*)sWhA)[i] = srcA[i];
            ((float4*)sWhB)[i] = srcB[i];
        }
        __syncthreads();

        #pragma unroll 1
        for (int oc = 0; oc < 5; oc++) {
            // ---- GEMM for this oc (fma + LDS streams) ----
            float y0v[4], y1v[4];
            #pragma unroll
            for (int u = 0; u < 4; u++) {
                const int o = oc * 4 + u;
                const float4* wA4 = (const float4*)(sWhA + o * 60);
                const float4* wB4 = (const float4*)(sWhB + o * 60);
                unsigned long long a0 = 0ull, a0b = 0ull, a1 = 0ull, a1b = 0ull;
                #pragma unroll
                for (int d = 0; d < 15; d++) {
                    float4 va = wA4[d];
                    float4 vb = wB4[d];
                    fma2(a0,  f2lo(va), h2[2*d]);
                    fma2(a0b, f2hi(va), h2[2*d+1]);
                    fma2(a1,  f2lo(vb), h2[2*d]);
                    fma2(a1b, f2hi(vb), h2[2*d+1]);
                }
                add2(a0, a0b);                   // pairwise merge in f32x2
                add2(a1, a1b);
                float pA, qA, pB, qB;
                unpack2(a0, pA, qA);
                unpack2(a1, pB, qB);
                float accA = (pA + qA) + sbh[k*20 + o];
                float accB = (pB + qB) + sbh[(k+20)*20 + o];
                y0v[u] = fmaxf(accA, 0.f) * 2.f;
                y1v[u] = fmaxf(accB, 0.f) * 2.f;
            }

            // ---- RNG for NEXT step (independent of GEMM above: interleaves) ----
            uint32_t tfn[8];
            {
                int noc = oc + 1, nk = k;
                if (noc == 5) { noc = 0; nk = k + 1; }   // k=20 garbage is unused
                uint32_t nbase = (unsigned)nk * BT20 + base_b + (unsigned)(noc * 4);
                #pragma unroll
                for (int u = 0; u < 4; u++) {
                    tfn[2*u]   = tf_bits(nbase + (unsigned)u,         one);
                    tfn[2*u+1] = tf_bits(nbase + (unsigned)u + HALFN, one);
                }
            }

            // ---- apply mask from PREVIOUS pipeline stage, store ----
            #pragma unroll
            for (int u = 0; u < 4; u++) {
                y0v[u] = ((int)tfc[2*u]   >= 0) ? y0v[u] : 0.f;
                y1v[u] = ((int)tfc[2*u+1] >= 0) ? y1v[u] : 0.f;
            }
            float4 v0 = make_float4(y0v[0], y0v[1], y0v[2], y0v[3]);
            float4 v1 = make_float4(y1v[0], y1v[1], y1v[2], y1v[3]);
            *(float4*)(out + (size_t)k        * BT20 + base_b + oc * 4) = v0;
            *(float4*)(out + (size_t)(k + 20) * BT20 + base_b + oc * 4) = v1;

            #pragma unroll
            for (int i = 0; i < 8; i++) tfc[i] = tfn[i];
        }
    }
}

extern "C" void kernel_launch(void* const* d_in, const int* in_sizes, int n_in,
                              void* d_out, int out_size) {
    const float* x  = (const float*)d_in[0];   // [131072, 20]
    const float* W1 = (const float*)d_in[1];   // [60, 20]
    const float* b1 = (const float*)d_in[2];   // [60]
    const float* Wh = (const float*)d_in[3];   // [40, 20, 60]
    const float* bh = (const float*)d_in[4];   // [40, 20]
    float* out = (float*)d_out;                // [40, 131072, 1, 20]

    const int rows = in_sizes[0] / 20;         // 131072
    dim3 grid(rows / TPB), block(TPB);
    fused_mlp_dropout<<<grid, block>>>(x, W1, b1, Wh, bh, out, 1u);
}